// round 5
// baseline (speedup 1.0000x reference)
#include <cuda_runtime.h>
#include <cuda_bf16.h>
#include <cstdint>

#define N_TOKENS  131072
#define NUM_CODES 1024
#define CODE_DIM  64
#define DECAY     0.99f
#define OMD       0.01f
#define EPS       1e-5f

#define OUT_Q     0
#define OUT_IDX   (N_TOKENS * CODE_DIM)
#define OUT_LOSS  (OUT_IDX + N_TOKENS)
#define OUT_CB    (OUT_LOSS + 1)
#define OUT_CS    (OUT_CB + NUM_CODES * CODE_DIM)
#define OUT_EMA   (OUT_CS + NUM_CODES)

#define MARGIN 2.0f
#define CAP    16
#define CHUNK  64
#define NCHUNK 16

// ---------------- device scratch ----------------
__device__ __align__(16) __nv_bfloat16 g_cbh[NUM_CODES * CODE_DIM];
__device__ float g_dw[NUM_CODES * CODE_DIM];
__device__ float g_counts[NUM_CODES];
__device__ float g_cnorm[NUM_CODES];
__device__ float g_inv[NUM_CODES];
__device__ float g_loss;

// ---------------- helpers ----------------
__device__ __forceinline__ uint32_t smem_u32(const void* p) {
    uint32_t a;
    asm("{ .reg .u64 t; cvta.to.shared.u64 t, %1; cvt.u32.u64 %0, t; }" : "=r"(a) : "l"(p));
    return a;
}
__device__ __forceinline__ void ldsm_x4(uint32_t& r0, uint32_t& r1, uint32_t& r2,
                                        uint32_t& r3, uint32_t addr) {
    asm volatile("ldmatrix.sync.aligned.m8n8.x4.shared.b16 {%0,%1,%2,%3}, [%4];"
                 : "=r"(r0), "=r"(r1), "=r"(r2), "=r"(r3) : "r"(addr));
}
__device__ __forceinline__ void mma16816(float* c, const uint32_t* a,
                                         uint32_t b0, uint32_t b1) {
    asm volatile(
        "mma.sync.aligned.m16n8k16.row.col.f32.bf16.bf16.f32 "
        "{%0,%1,%2,%3}, {%4,%5,%6,%7}, {%8,%9}, {%0,%1,%2,%3};"
        : "+f"(c[0]), "+f"(c[1]), "+f"(c[2]), "+f"(c[3])
        : "r"(a[0]), "r"(a[1]), "r"(a[2]), "r"(a[3]), "r"(b0), "r"(b1));
}
__device__ __forceinline__ unsigned bf2u(float a, float b) {
    __nv_bfloat162 p(__float2bfloat16_rn(a), __float2bfloat16_rn(b));
    return *(unsigned*)&p;
}

// ---------------- prep: codebook bf16 + cnorm + zero scratch ----------------
__global__ void prep_cb_kernel(const float4* __restrict__ cb4) {
    int i = blockIdx.x * 256 + threadIdx.x;   // 16384 threads
    float4 v = cb4[i];
    uint2 o;
    o.x = bf2u(v.x, v.y);
    o.y = bf2u(v.z, v.w);
    ((uint2*)g_cbh)[i] = o;
    ((float4*)g_dw)[i] = make_float4(0.f, 0.f, 0.f, 0.f);
    if (i < NUM_CODES) {
        g_counts[i] = 0.0f;
        float s = 0.0f;
        const float4* c = cb4 + i * 16;
#pragma unroll
        for (int j = 0; j < 16; j++) {
            float4 w = c[j];
            s += w.x * w.x + w.y * w.y + w.z * w.z + w.w * w.w;
        }
        g_cnorm[i] = s;
    }
    if (i == 0) g_loss = 0.0f;
}

// ---------------- assign ----------------
// 128 threads (4 warps), 128 tokens/CTA, 1024 CTAs. 16 chunks of 64 codes.
// Epilogue fused per-nt so only acc[2][4] is live -> no spills.
__global__ void __launch_bounds__(128)
assign_kernel(const float4* __restrict__ z4, const float4* __restrict__ cb4,
              float* __restrict__ out) {
    __shared__ __align__(16) unsigned char As[128 * 144];
    __shared__ __align__(16) unsigned char Bs[64 * 144];
    __shared__ float cns[CHUNK];
    __shared__ unsigned cnt[128];
    __shared__ unsigned short cand[128 * CAP];

    const int tid  = threadIdx.x;
    const int w    = tid >> 5;
    const int lane = tid & 31;
    const int base = blockIdx.x * 128;
    const uint32_t AsA = smem_u32(As);
    const uint32_t BsA = smem_u32(Bs);

    cnt[tid] = 0u;

    // ---- stage z tile: fp32 global -> bf16 As (rows 128B, stride 144)
    {
#pragma unroll
        for (int i = 0; i < 16; i++) {
            int l = tid + i * 128;             // 2048 float4
            int row = l >> 4, j = l & 15;
            float4 v = z4[(size_t)(base + row) * 16 + j];
            uint2 o; o.x = bf2u(v.x, v.y); o.y = bf2u(v.z, v.w);
            *(uint2*)(As + row * 144 + j * 8) = o;
        }
    }

    // ---- prefetch B chunk 0 (bf16)
    uint4 pre[4];
    float cnpre = 0.0f;
    {
        const uint4* src = (const uint4*)g_cbh;
#pragma unroll
        for (int i = 0; i < 4; i++) {
            int l = tid + i * 128;
            int row = l >> 3, j = l & 7;
            pre[i] = src[row * 8 + j];
        }
        if (tid < CHUNK) cnpre = g_cnorm[tid];
    }

    __syncthreads();   // As visible

    // ---- load A fragments once: af[mt][ks][4]
    uint32_t af[2][4][4];
#pragma unroll
    for (int mt = 0; mt < 2; mt++) {
#pragma unroll
        for (int ks = 0; ks < 4; ks++) {
            uint32_t addr = AsA + (w * 32 + mt * 16 + (lane & 15)) * 144
                          + ((lane >> 4) << 4) + ks * 32;
            ldsm_x4(af[mt][ks][0], af[mt][ks][1], af[mt][ks][2], af[mt][ks][3], addr);
        }
    }

    float rb[4];       // running approx min per (mt, ap) token row
#pragma unroll
    for (int i = 0; i < 4; i++) rb[i] = 3.0e38f;

    for (int c = 0; c < NCHUNK; c++) {
        const int kb = c * CHUNK;
        __syncthreads();   // prior chunk done reading Bs/cns
#pragma unroll
        for (int i = 0; i < 4; i++) {
            int l = tid + i * 128;
            int row = l >> 3, j = l & 7;
            *(uint4*)(Bs + row * 144 + j * 16) = pre[i];
        }
        if (tid < CHUNK) cns[tid] = cnpre;
        __syncthreads();   // Bs ready

        if (c < NCHUNK - 1) {
            const uint4* src = (const uint4*)(g_cbh + (size_t)(kb + CHUNK) * CODE_DIM);
#pragma unroll
            for (int i = 0; i < 4; i++) {
                int l = tid + i * 128;
                int row = l >> 3, j = l & 7;
                pre[i] = src[row * 8 + j];
            }
            if (tid < CHUNK) cnpre = g_cnorm[kb + CHUNK + tid];
        }

        // ---- per-nt: MMA + fused epilogue (acc footprint = 8 regs)
#pragma unroll
        for (int nt = 0; nt < 8; nt++) {
            uint32_t b[8];
            uint32_t baddr = BsA + (nt * 8 + (lane & 7)) * 144 + ((lane >> 3) << 4);
            ldsm_x4(b[0], b[1], b[2], b[3], baddr);        // ksteps 0,1
            ldsm_x4(b[4], b[5], b[6], b[7], baddr + 64);   // ksteps 2,3

            float acc[2][4];
#pragma unroll
            for (int mt = 0; mt < 2; mt++) {
                acc[mt][0] = acc[mt][1] = acc[mt][2] = acc[mt][3] = 0.0f;
                mma16816(acc[mt], af[mt][0], b[0], b[1]);
                mma16816(acc[mt], af[mt][1], b[2], b[3]);
                mma16816(acc[mt], af[mt][2], b[4], b[5]);
                mma16816(acc[mt], af[mt][3], b[6], b[7]);
            }

            float2 cnv = *(const float2*)&cns[nt * 8 + 2 * (lane & 3)];
#pragma unroll
            for (int mt = 0; mt < 2; mt++) {
#pragma unroll
                for (int ap = 0; ap < 2; ap++) {
                    float s0 = fmaf(-2.0f, acc[mt][ap * 2 + 0], cnv.x);
                    float s1 = fmaf(-2.0f, acc[mt][ap * 2 + 1], cnv.y);
                    float mn = fminf(s0, s1);
                    mn = fminf(mn, __shfl_xor_sync(0xffffffffu, mn, 1));
                    mn = fminf(mn, __shfl_xor_sync(0xffffffffu, mn, 2));
                    float r = fminf(rb[mt * 2 + ap], mn);
                    rb[mt * 2 + ap] = r;
                    float thr = r + MARGIN;
                    int tok_l = w * 32 + mt * 16 + (lane >> 2) + 8 * ap;
                    if (s0 <= thr) {
                        unsigned slot = atomicAdd(&cnt[tok_l], 1u);
                        if (slot < CAP)
                            cand[tok_l * CAP + slot] =
                                (unsigned short)(kb + nt * 8 + 2 * (lane & 3));
                    }
                    if (s1 <= thr) {
                        unsigned slot = atomicAdd(&cnt[tok_l], 1u);
                        if (slot < CAP)
                            cand[tok_l * CAP + slot] =
                                (unsigned short)(kb + nt * 8 + 2 * (lane & 3) + 1);
                    }
                }
            }
        }
    }
    __syncthreads();

    // ---- phase B: exact fp32 rescore (thread owns token base+tid; z row stays in L1)
    const int tok = base + tid;
    const float4* zsrc = z4 + (size_t)tok * 16;

    float zn = 0.0f;
#pragma unroll
    for (int j = 0; j < 16; j++) {
        float4 v = zsrc[j];
        zn += v.x * v.x + v.y * v.y + v.z * v.z + v.w * v.w;
    }

    float best = 3.0e38f;
    int   bk   = 0;
    unsigned n = cnt[tid];
    if (n > 0 && n <= CAP) {
        for (unsigned u = 0; u < n; u++) {
            int k = cand[tid * CAP + u];
            const float4* cr = cb4 + (size_t)k * 16;
            float dot = 0.0f;
#pragma unroll
            for (int j = 0; j < 16; j++) {
                float4 a = zsrc[j];
                float4 v = cr[j];
                dot += a.x * v.x + a.y * v.y + a.z * v.z + a.w * v.w;
            }
            float s = fmaf(-2.0f, dot, g_cnorm[k]);
            if (s < best || (s == best && k < bk)) { best = s; bk = k; }
        }
    } else {
        for (int k = 0; k < NUM_CODES; k++) {
            const float4* cr = cb4 + (size_t)k * 16;
            float dot = 0.0f;
#pragma unroll
            for (int j = 0; j < 16; j++) {
                float4 a = zsrc[j];
                float4 v = cr[j];
                dot += a.x * v.x + a.y * v.y + a.z * v.z + a.w * v.w;
            }
            float s = fmaf(-2.0f, dot, g_cnorm[k]);
            if (s < best) { best = s; bk = k; }
        }
    }

    // ---- outputs + scatter stats
    out[OUT_IDX + tok] = (float)bk;
    atomicAdd(&g_counts[bk], 1.0f);
    float4* outq = (float4*)out;   // OUT_Q == 0
    const float4* cbest = cb4 + (size_t)bk * 16;
    float* dwp = &g_dw[bk * 64];
#pragma unroll
    for (int j = 0; j < 16; j++) {
        float4 a = zsrc[j];
        outq[(size_t)tok * 16 + j] = cbest[j];
        atomicAdd(&dwp[4 * j + 0], a.x);
        atomicAdd(&dwp[4 * j + 1], a.y);
        atomicAdd(&dwp[4 * j + 2], a.z);
        atomicAdd(&dwp[4 * j + 3], a.w);
    }

    float lp = zn + best;   // exact d2min
#pragma unroll
    for (int off = 16; off > 0; off >>= 1)
        lp += __shfl_down_sync(0xffffffffu, lp, off);
    if (lane == 0) atomicAdd(&g_loss, lp);
}

// ---------------- finalize A: small per-code stats + loss ----------------
__global__ void finalize_a_kernel(const float* __restrict__ cs_in,
                                  float* __restrict__ out) {
    __shared__ float s[1024];
    int k = threadIdx.x;
    float ncs = DECAY * cs_in[k] + OMD * g_counts[k];
    s[k] = ncs;
    __syncthreads();
    for (int st = 512; st > 0; st >>= 1) {
        if (k < st) s[k] += s[k + st];
        __syncthreads();
    }
    float n   = s[0];
    float csk = (ncs + EPS) / (n + NUM_CODES * EPS) * n;
    out[OUT_CS + k] = ncs;
    g_inv[k] = 1.0f / csk;
    if (k == 0) out[OUT_LOSS] = g_loss * (1.0f / (float)(N_TOKENS * CODE_DIM));
}

// ---------------- finalize B: parallel EMA + codebook update ----------------
__global__ void finalize_b_kernel(const float* __restrict__ ema_in,
                                  float* __restrict__ out) {
    int i = blockIdx.x * 256 + threadIdx.x;   // 65536 threads
    float e = DECAY * ema_in[i] + OMD * g_dw[i];
    out[OUT_EMA + i] = e;
    out[OUT_CB + i]  = e * g_inv[i >> 6];
}

extern "C" void kernel_launch(void* const* d_in, const int* in_sizes, int n_in,
                              void* d_out, int out_size) {
    const float* z   = (const float*)d_in[0];
    const float* cb  = (const float*)d_in[1];
    const float* cs  = (const float*)d_in[2];
    const float* ema = (const float*)d_in[3];
    float* out = (float*)d_out;

    prep_cb_kernel<<<64, 256>>>((const float4*)cb);
    assign_kernel<<<1024, 128>>>((const float4*)z, (const float4*)cb, out);
    finalize_a_kernel<<<1, 1024>>>(cs, out);
    finalize_b_kernel<<<256, 256>>>(ema, out);
}